// round 11
// baseline (speedup 1.0000x reference)
#include <cuda_runtime.h>
#include <cuda_fp16.h>
#include <cstdint>

// ---------------- problem constants -----------------------------------------
#define NT 2048
#define NE 8
#define DM 1024
#define DF 4096
#define TOPK 2
#define NA (NT*TOPK)

// ---------------- tiling -----------------------------------------------------
#define BM 128
#define BK 32
#define A_ROW_B 80                 // 64B data + 16B pad (conflict-free ldsm)
#define B_ROW_B 272                // 256B data + 16B pad
#define ST_A (BM * A_ROW_B)        // 10240
#define ST_B (BK * B_ROW_B)        // 8704
#define STAGE (ST_A + ST_B)        // 18944: A | B
#define NSTG 4
#define SMEMSZ (NSTG*STAGE)        // 75776

// ---------------- device scratch ---------------------------------------------
__device__ int   g_cnt[NE];
__device__ int   g_tok[NE * NA];
__device__ int   g_asg[NE * NA];
__device__ float g_obuf[(size_t)NA * DM];
// fp16 operands
__device__ __half g_xf[(size_t)NT * DM];
__device__ __half g_hf[(size_t)NA * DF];
__device__ __half g_w1f[(size_t)NE * DM * DF];
__device__ __half g_w2f[(size_t)NE * DM * DF];
__device__ __half g_w3f[(size_t)NE * DF * DM];

// ---------------- helpers ----------------------------------------------------
__device__ __forceinline__ uint32_t smem_u32(const void* p) {
    uint32_t a;
    asm("{ .reg .u64 t; cvta.to.shared.u64 t, %1; cvt.u32.u64 %0, t; }" : "=r"(a) : "l"(p));
    return a;
}
__device__ __forceinline__ void ldsm_x4(uint32_t* r, uint32_t addr) {
    asm volatile("ldmatrix.sync.aligned.m8n8.x4.shared.b16 {%0,%1,%2,%3}, [%4];"
                 : "=r"(r[0]), "=r"(r[1]), "=r"(r[2]), "=r"(r[3]) : "r"(addr));
}
__device__ __forceinline__ void ldsm_x4_t(uint32_t* r, uint32_t addr) {
    asm volatile("ldmatrix.sync.aligned.m8n8.x4.trans.shared.b16 {%0,%1,%2,%3}, [%4];"
                 : "=r"(r[0]), "=r"(r[1]), "=r"(r[2]), "=r"(r[3]) : "r"(addr));
}
__device__ __forceinline__ void mma_f16(float* d, const uint32_t* a, uint32_t b0, uint32_t b1) {
    asm volatile(
        "mma.sync.aligned.m16n8k16.row.col.f32.f16.f16.f32 "
        "{%0,%1,%2,%3}, {%4,%5,%6,%7}, {%8,%9}, {%0,%1,%2,%3};"
        : "+f"(d[0]), "+f"(d[1]), "+f"(d[2]), "+f"(d[3])
        : "r"(a[0]), "r"(a[1]), "r"(a[2]), "r"(a[3]), "r"(b0), "r"(b1));
}
__device__ __forceinline__ void cp16(uint32_t dst, const void* src, bool pred) {
    int sz = pred ? 16 : 0;
    asm volatile("cp.async.cg.shared.global [%0], [%1], 16, %2;"
                 :: "r"(dst), "l"(src), "r"(sz) : "memory");
}
#define CP_COMMIT asm volatile("cp.async.commit_group;" ::: "memory")
#define CP_WAIT2  asm volatile("cp.async.wait_group 2;" ::: "memory")

// ---------------- routing ----------------------------------------------------
__global__ void reset_counts_k() { if (threadIdx.x < NE) g_cnt[threadIdx.x] = 0; }

__global__ void route_k(const int* __restrict__ idx) {
    int a = blockIdx.x * blockDim.x + threadIdx.x;
    if (a >= NA) return;
    int e = idx[a];
    int p = atomicAdd(&g_cnt[e], 1);
    g_tok[e * NA + p] = a >> 1;
    g_asg[e * NA + p] = a;
}

// ---------------- conversion: fp32 -> fp16 ------------------------------------
__global__ void __launch_bounds__(256) cvt_f16_k(const float4* __restrict__ src,
                                                 uint2* __restrict__ dst, int n4) {
    int i = blockIdx.x * blockDim.x + threadIdx.x;
    if (i >= n4) return;
    float4 v = src[i];
    __half2 p0 = __floats2half2_rn(v.x, v.y);
    __half2 p1 = __floats2half2_rn(v.z, v.w);
    uint2 r; r.x = *(uint32_t*)&p0; r.y = *(uint32_t*)&p1;
    dst[i] = r;
}

// ---------------- GEMM: pure fp16, BK=32, cp.async 4-stage ring ---------------
template<bool UP>
__global__ void __launch_bounds__(128, 2) gemm_k(const float* __restrict__ ew) {
    constexpr int KTOT = UP ? DM : DF;
    constexpr int NS   = KTOT / BK;
    const int e   = blockIdx.z;
    const int cnt = g_cnt[e];
    const int m0  = blockIdx.y * BM;
    if (m0 >= cnt) return;
    const int bx  = blockIdx.x;

    extern __shared__ char smem[];
    const uint32_t sbase = smem_u32(smem);
    const int tid  = threadIdx.x;
    const int lane = tid & 31;
    const int wid  = tid >> 5;
    const int wm   = wid & 1;
    const int wn   = wid >> 1;

    // ---- A cp.async: row tid, 32 fp16 (64B) per stage ----
    const int am = m0 + tid;
    const bool av = (am < cnt);
    const __half* paf;
    {
        int slot = av ? (UP ? g_tok[e * NA + am] : g_asg[e * NA + am]) : 0;
        paf = (UP ? g_xf : g_hf) + (size_t)slot * (UP ? DM : DF);
    }
    const uint32_t a_dst = (uint32_t)(tid * A_ROW_B);

    // ---- B cp.async: k-row tid>>2, 32 n (64B) per stage ----
    const int bkr = tid >> 2;
    const int bnc = (tid & 3) * 32;
    const __half* pbf;
    size_t bld;
    if (UP) {
        bld = DF;
        const __half* w = (bnc < 64) ? g_w1f : g_w2f;
        pbf = w + (size_t)e * DM * DF + (size_t)bkr * DF + (size_t)bx * 64 + (bnc & 63);
    } else {
        bld = DM;
        pbf = g_w3f + (size_t)e * DF * DM + (size_t)bkr * DM + (size_t)bx * 128 + bnc;
    }
    const uint32_t b_dst = (uint32_t)(bkr * B_ROW_B + bnc * 2);

    auto issue = [&](int s) {
        const uint32_t st = sbase + (uint32_t)(s & (NSTG - 1)) * STAGE;
        const int k0 = s * BK;
        cp16(st + a_dst,      paf + k0,      av);
        cp16(st + a_dst + 16, paf + k0 + 8,  av);
        cp16(st + a_dst + 32, paf + k0 + 16, av);
        cp16(st + a_dst + 48, paf + k0 + 24, av);
        const __half* q = pbf + (size_t)k0 * bld;
        const uint32_t bb = st + ST_A;
        cp16(bb + b_dst,      q,      true);
        cp16(bb + b_dst + 16, q + 8,  true);
        cp16(bb + b_dst + 32, q + 16, true);
        cp16(bb + b_dst + 48, q + 24, true);
    };

    float acc[4][8][4];
    #pragma unroll
    for (int i = 0; i < 4; i++)
        #pragma unroll
        for (int j = 0; j < 8; j++)
            #pragma unroll
            for (int k = 0; k < 4; k++) acc[i][j][k] = 0.f;

    // ldmatrix constants
    const uint32_t a_row_b = (uint32_t)(wm * 64 + (lane & 15));
    const uint32_t a_koff  = (uint32_t)((lane >> 4) * 16);
    const uint32_t b_krow  = (uint32_t)(((lane >> 3) & 1) * 8 + (lane & 7));
    const uint32_t b_nhalf = (uint32_t)((lane >> 4) * 8);
    int nof[4];
    if (UP) {
        nof[0] = wn * 32;      nof[1] = wn * 32 + 16;        // gate
        nof[2] = 64 + wn * 32; nof[3] = 64 + wn * 32 + 16;   // value
    } else {
        nof[0] = wn * 64;      nof[1] = wn * 64 + 16;
        nof[2] = wn * 64 + 32; nof[3] = wn * 64 + 48;
    }

    issue(0); CP_COMMIT;
    issue(1); CP_COMMIT;
    issue(2); CP_COMMIT;

    #pragma unroll 1
    for (int s = 0; s < NS; s++) {
        CP_WAIT2;
        __syncthreads();
        if (s + 3 < NS) issue(s + 3);
        CP_COMMIT;

        const uint32_t uS = sbase + (uint32_t)(s & (NSTG - 1)) * STAGE;
        #pragma unroll
        for (int ks = 0; ks < 2; ks++) {
            uint32_t af[4][4];
            #pragma unroll
            for (int mt = 0; mt < 4; mt++) {
                uint32_t addr = uS + (a_row_b + mt * 16) * A_ROW_B + ks * 32 + a_koff;
                ldsm_x4(af[mt], addr);
            }
            uint32_t bf[4][4];
            #pragma unroll
            for (int g = 0; g < 4; g++) {
                uint32_t addr = uS + ST_A + (ks * 16 + b_krow) * B_ROW_B
                              + ((uint32_t)nof[g] + b_nhalf) * 2;
                ldsm_x4_t(bf[g], addr);
            }
            #pragma unroll
            for (int mt = 0; mt < 4; mt++)
                #pragma unroll
                for (int g = 0; g < 4; g++)
                    #pragma unroll
                    for (int j = 0; j < 2; j++)
                        mma_f16(acc[mt][g * 2 + j], af[mt], bf[g][j * 2], bf[g][j * 2 + 1]);
        }
    }

    // ---- epilogue ----
    const int qrow = lane >> 2;
    const int qcol = (lane & 3) * 2;
    #pragma unroll
    for (int mt = 0; mt < 4; mt++) {
        #pragma unroll
        for (int h = 0; h < 2; h++) {
            int m = m0 + wm * 64 + mt * 16 + qrow + 8 * h;
            if (m >= cnt) continue;
            int a = g_asg[e * NA + m];
            if (UP) {
                __half* hrow = g_hf + (size_t)a * DF + bx * 64 + wn * 32;
                #pragma unroll
                for (int g = 0; g < 2; g++)
                    #pragma unroll
                    for (int j = 0; j < 2; j++) {
                        float g0 = acc[mt][g * 2 + j][h * 2];
                        float g1 = acc[mt][g * 2 + j][h * 2 + 1];
                        float v0 = acc[mt][4 + g * 2 + j][h * 2];
                        float v1 = acc[mt][4 + g * 2 + j][h * 2 + 1];
                        float r0 = v0 * g0 / (1.f + __expf(-g0));
                        float r1 = v1 * g1 / (1.f + __expf(-g1));
                        __half2 ph = __floats2half2_rn(r0, r1);
                        *(__half2*)(hrow + g * 16 + j * 8 + qcol) = ph;
                    }
            } else {
                float sc = ew[a];
                float* orow = g_obuf + (size_t)a * DM + bx * 128 + wn * 64;
                #pragma unroll
                for (int g = 0; g < 4; g++)
                    #pragma unroll
                    for (int j = 0; j < 2; j++) {
                        float2 r;
                        r.x = acc[mt][g * 2 + j][h * 2] * sc;
                        r.y = acc[mt][g * 2 + j][h * 2 + 1] * sc;
                        *(float2*)(orow + g * 16 + j * 8 + qcol) = r;
                    }
            }
        }
    }
}

// ---------------- combine -----------------------------------------------------
__global__ void combine_k(float* __restrict__ out) {
    int i = blockIdx.x * blockDim.x + threadIdx.x;
    const int W = DM / 4;
    if (i >= NT * W) return;
    int t = i / W;
    int c = i - t * W;
    const float4* buf = (const float4*)g_obuf;
    float4 a0 = buf[(size_t)(2 * t) * W + c];
    float4 a1 = buf[(size_t)(2 * t + 1) * W + c];
    ((float4*)out)[i] = make_float4(a0.x + a1.x, a0.y + a1.y, a0.z + a1.z, a0.w + a1.w);
}

// ---------------- launch ------------------------------------------------------
extern "C" void kernel_launch(void* const* d_in, const int* in_sizes, int n_in,
                              void* d_out, int out_size) {
    const float* x   = (const float*)d_in[0];
    const int*   idx = (const int*)d_in[1];
    const float* ew  = (const float*)d_in[2];
    const float* w1  = (const float*)d_in[3];
    const float* w2  = (const float*)d_in[4];
    const float* w3  = (const float*)d_in[5];
    float* out = (float*)d_out;

    cudaFuncSetAttribute(gemm_k<true>,  cudaFuncAttributeMaxDynamicSharedMemorySize, SMEMSZ);
    cudaFuncSetAttribute(gemm_k<false>, cudaFuncAttributeMaxDynamicSharedMemorySize, SMEMSZ);

    reset_counts_k<<<1, 32>>>();
    route_k<<<NA / 256, 256>>>(idx);

    {
        __half *xf, *w1f, *w2f, *w3f;
        cudaGetSymbolAddress((void**)&xf,  g_xf);
        cudaGetSymbolAddress((void**)&w1f, g_w1f);
        cudaGetSymbolAddress((void**)&w2f, g_w2f);
        cudaGetSymbolAddress((void**)&w3f, g_w3f);
        int nw4 = NE * DM * DF / 4;
        int nx4 = NT * DM / 4;
        cvt_f16_k<<<(nx4 + 255) / 256, 256>>>((const float4*)x,  (uint2*)xf,  nx4);
        cvt_f16_k<<<(nw4 + 255) / 256, 256>>>((const float4*)w1, (uint2*)w1f, nw4);
        cvt_f16_k<<<(nw4 + 255) / 256, 256>>>((const float4*)w2, (uint2*)w2f, nw4);
        cvt_f16_k<<<(nw4 + 255) / 256, 256>>>((const float4*)w3, (uint2*)w3f, nw4);
    }

    gemm_k<true><<<dim3(64, NA / BM, NE), 128, SMEMSZ>>>(ew);
    gemm_k<false><<<dim3(8, NA / BM, NE), 128, SMEMSZ>>>(ew);

    combine_k<<<(NT * (DM / 4) + 255) / 256, 256>>>(out);
}

// round 12
// speedup vs baseline: 1.2201x; 1.2201x over previous
#include <cuda_runtime.h>
#include <cuda_fp16.h>
#include <cstdint>

// ---------------- problem constants -----------------------------------------
#define NT 2048
#define NE 8
#define DM 1024
#define DF 4096
#define TOPK 2
#define NA (NT*TOPK)

// ---------------- tiling -----------------------------------------------------
#define BM 128
#define BK 16
#define A_ROW_B 48                 // 32B data + 16B pad (conflict-free ldsm)
#define B_ROW_B 272                // 256B data + 16B pad
#define ST_A (BM * A_ROW_B)        // 6144
#define ST_B (BK * B_ROW_B)        // 4352
#define STAGE (ST_A + ST_B)        // 10496: A | B
#define NSTG 4
#define SMEMSZ (NSTG*STAGE)        // 41984

// ---------------- device scratch ---------------------------------------------
__device__ int   g_cnt[NE];
__device__ int   g_tok[NE * NA];
__device__ int   g_asg[NE * NA];
__device__ float g_obuf[(size_t)NA * DM];
// fp16 operands
__device__ __half g_xf[(size_t)NT * DM];
__device__ __half g_hf[(size_t)NA * DF];
__device__ __half g_w1f[(size_t)NE * DM * DF];
__device__ __half g_w2f[(size_t)NE * DM * DF];
__device__ __half g_w3f[(size_t)NE * DF * DM];

// ---------------- helpers ----------------------------------------------------
__device__ __forceinline__ uint32_t smem_u32(const void* p) {
    uint32_t a;
    asm("{ .reg .u64 t; cvta.to.shared.u64 t, %1; cvt.u32.u64 %0, t; }" : "=r"(a) : "l"(p));
    return a;
}
__device__ __forceinline__ void ldsm_x4(uint32_t* r, uint32_t addr) {
    asm volatile("ldmatrix.sync.aligned.m8n8.x4.shared.b16 {%0,%1,%2,%3}, [%4];"
                 : "=r"(r[0]), "=r"(r[1]), "=r"(r[2]), "=r"(r[3]) : "r"(addr));
}
__device__ __forceinline__ void ldsm_x4_t(uint32_t* r, uint32_t addr) {
    asm volatile("ldmatrix.sync.aligned.m8n8.x4.trans.shared.b16 {%0,%1,%2,%3}, [%4];"
                 : "=r"(r[0]), "=r"(r[1]), "=r"(r[2]), "=r"(r[3]) : "r"(addr));
}
__device__ __forceinline__ void mma_f16(float* d, const uint32_t* a, uint32_t b0, uint32_t b1) {
    asm volatile(
        "mma.sync.aligned.m16n8k16.row.col.f32.f16.f16.f32 "
        "{%0,%1,%2,%3}, {%4,%5,%6,%7}, {%8,%9}, {%0,%1,%2,%3};"
        : "+f"(d[0]), "+f"(d[1]), "+f"(d[2]), "+f"(d[3])
        : "r"(a[0]), "r"(a[1]), "r"(a[2]), "r"(a[3]), "r"(b0), "r"(b1));
}
__device__ __forceinline__ void cp16(uint32_t dst, const void* src, bool pred) {
    int sz = pred ? 16 : 0;
    asm volatile("cp.async.cg.shared.global [%0], [%1], 16, %2;"
                 :: "r"(dst), "l"(src), "r"(sz) : "memory");
}
#define CP_COMMIT asm volatile("cp.async.commit_group;" ::: "memory")
#define CP_WAIT2  asm volatile("cp.async.wait_group 2;" ::: "memory")

// ---------------- routing ----------------------------------------------------
__global__ void reset_counts_k() { if (threadIdx.x < NE) g_cnt[threadIdx.x] = 0; }

__global__ void route_k(const int* __restrict__ idx) {
    int a = blockIdx.x * blockDim.x + threadIdx.x;
    if (a >= NA) return;
    int e = idx[a];
    int p = atomicAdd(&g_cnt[e], 1);
    g_tok[e * NA + p] = a >> 1;
    g_asg[e * NA + p] = a;
}

// ---------------- conversion: fp32 -> fp16, 32B/thread, grid-stride -----------
__global__ void __launch_bounds__(256) cvt_f16_k(const float4* __restrict__ src,
                                                 uint2* __restrict__ dst, int n4) {
    int stride = gridDim.x * blockDim.x;
    for (int i = blockIdx.x * blockDim.x + threadIdx.x; i < n4; i += stride) {
        float4 v = src[i];
        __half2 p0 = __floats2half2_rn(v.x, v.y);
        __half2 p1 = __floats2half2_rn(v.z, v.w);
        uint2 r; r.x = *(uint32_t*)&p0; r.y = *(uint32_t*)&p1;
        dst[i] = r;
    }
}

// ---------------- GEMM: pure fp16, BK=16, cp.async 4-stage ring ---------------
template<bool UP>
__global__ void __launch_bounds__(128, 2) gemm_k(const float* __restrict__ ew) {
    constexpr int KTOT = UP ? DM : DF;
    constexpr int NS   = KTOT / BK;
    const int e   = blockIdx.z;
    const int cnt = g_cnt[e];
    const int m0  = blockIdx.y * BM;
    if (m0 >= cnt) return;
    const int bx  = blockIdx.x;

    extern __shared__ char smem[];
    const uint32_t sbase = smem_u32(smem);
    const int tid  = threadIdx.x;
    const int lane = tid & 31;
    const int wid  = tid >> 5;
    const int wm   = wid & 1;
    const int wn   = wid >> 1;

    // ---- A cp.async: row tid, 16 fp16 (32B) per stage ----
    const int am = m0 + tid;
    const bool av = (am < cnt);
    const __half* paf;
    {
        int slot = av ? (UP ? g_tok[e * NA + am] : g_asg[e * NA + am]) : 0;
        paf = (UP ? g_xf : g_hf) + (size_t)slot * (UP ? DM : DF);
    }
    const uint32_t a_dst = (uint32_t)(tid * A_ROW_B);

    // ---- B cp.async: k-row tid>>3, 16 n (32B) per stage ----
    const int bkr = tid >> 3;
    const int bnc = (tid & 7) * 16;
    const __half* pbf;
    size_t bld;
    if (UP) {
        bld = DF;
        const __half* w = (bnc < 64) ? g_w1f : g_w2f;
        pbf = w + (size_t)e * DM * DF + (size_t)bkr * DF + (size_t)bx * 64 + (bnc & 63);
    } else {
        bld = DM;
        pbf = g_w3f + (size_t)e * DF * DM + (size_t)bkr * DM + (size_t)bx * 128 + bnc;
    }
    const uint32_t b_dst = (uint32_t)(bkr * B_ROW_B + bnc * 2);

    auto issue = [&](int s) {
        const uint32_t st = sbase + (uint32_t)(s & (NSTG - 1)) * STAGE;
        const int k0 = s * BK;
        cp16(st + a_dst,      paf + k0,     av);
        cp16(st + a_dst + 16, paf + k0 + 8, av);
        const __half* q = pbf + (size_t)k0 * bld;
        const uint32_t bb = st + ST_A;
        cp16(bb + b_dst,      q,     true);
        cp16(bb + b_dst + 16, q + 8, true);
    };

    float acc[4][8][4];
    #pragma unroll
    for (int i = 0; i < 4; i++)
        #pragma unroll
        for (int j = 0; j < 8; j++)
            #pragma unroll
            for (int k = 0; k < 4; k++) acc[i][j][k] = 0.f;

    // ldmatrix constants
    const uint32_t a_row_b = (uint32_t)(wm * 64 + (lane & 15));
    const uint32_t a_koff  = (uint32_t)((lane >> 4) * 16);
    const uint32_t b_krow  = (uint32_t)(((lane >> 3) & 1) * 8 + (lane & 7));
    const uint32_t b_nhalf = (uint32_t)((lane >> 4) * 8);
    int nof[4];
    if (UP) {
        nof[0] = wn * 32;      nof[1] = wn * 32 + 16;        // gate
        nof[2] = 64 + wn * 32; nof[3] = 64 + wn * 32 + 16;   // value
    } else {
        nof[0] = wn * 64;      nof[1] = wn * 64 + 16;
        nof[2] = wn * 64 + 32; nof[3] = wn * 64 + 48;
    }

    issue(0); CP_COMMIT;
    issue(1); CP_COMMIT;
    issue(2); CP_COMMIT;

    #pragma unroll 1
    for (int s = 0; s < NS; s++) {
        CP_WAIT2;
        __syncthreads();
        if (s + 3 < NS) issue(s + 3);
        CP_COMMIT;

        const uint32_t uS = sbase + (uint32_t)(s & (NSTG - 1)) * STAGE;
        uint32_t af[4][4];
        #pragma unroll
        for (int mt = 0; mt < 4; mt++) {
            uint32_t addr = uS + (a_row_b + mt * 16) * A_ROW_B + a_koff;
            ldsm_x4(af[mt], addr);
        }
        uint32_t bf[4][4];
        #pragma unroll
        for (int g = 0; g < 4; g++) {
            uint32_t addr = uS + ST_A + b_krow * B_ROW_B + ((uint32_t)nof[g] + b_nhalf) * 2;
            ldsm_x4_t(bf[g], addr);
        }
        #pragma unroll
        for (int mt = 0; mt < 4; mt++)
            #pragma unroll
            for (int g = 0; g < 4; g++)
                #pragma unroll
                for (int j = 0; j < 2; j++)
                    mma_f16(acc[mt][g * 2 + j], af[mt], bf[g][j * 2], bf[g][j * 2 + 1]);
    }

    // ---- epilogue ----
    const int qrow = lane >> 2;
    const int qcol = (lane & 3) * 2;
    #pragma unroll
    for (int mt = 0; mt < 4; mt++) {
        #pragma unroll
        for (int h = 0; h < 2; h++) {
            int m = m0 + wm * 64 + mt * 16 + qrow + 8 * h;
            if (m >= cnt) continue;
            int a = g_asg[e * NA + m];
            if (UP) {
                __half* hrow = g_hf + (size_t)a * DF + bx * 64 + wn * 32;
                #pragma unroll
                for (int g = 0; g < 2; g++)
                    #pragma unroll
                    for (int j = 0; j < 2; j++) {
                        float g0 = acc[mt][g * 2 + j][h * 2];
                        float g1 = acc[mt][g * 2 + j][h * 2 + 1];
                        float v0 = acc[mt][4 + g * 2 + j][h * 2];
                        float v1 = acc[mt][4 + g * 2 + j][h * 2 + 1];
                        float r0 = v0 * g0 / (1.f + __expf(-g0));
                        float r1 = v1 * g1 / (1.f + __expf(-g1));
                        __half2 ph = __floats2half2_rn(r0, r1);
                        *(__half2*)(hrow + g * 16 + j * 8 + qcol) = ph;
                    }
            } else {
                float sc = ew[a];
                float* orow = g_obuf + (size_t)a * DM + bx * 128 + wn * 64;
                #pragma unroll
                for (int g = 0; g < 4; g++)
                    #pragma unroll
                    for (int j = 0; j < 2; j++) {
                        float2 r;
                        r.x = acc[mt][g * 2 + j][h * 2] * sc;
                        r.y = acc[mt][g * 2 + j][h * 2 + 1] * sc;
                        *(float2*)(orow + g * 16 + j * 8 + qcol) = r;
                    }
            }
        }
    }
}

// ---------------- combine -----------------------------------------------------
__global__ void combine_k(float* __restrict__ out) {
    int i = blockIdx.x * blockDim.x + threadIdx.x;
    const int W = DM / 4;
    if (i >= NT * W) return;
    int t = i / W;
    int c = i - t * W;
    const float4* buf = (const float4*)g_obuf;
    float4 a0 = buf[(size_t)(2 * t) * W + c];
    float4 a1 = buf[(size_t)(2 * t + 1) * W + c];
    ((float4*)out)[i] = make_float4(a0.x + a1.x, a0.y + a1.y, a0.z + a1.z, a0.w + a1.w);
}

// ---------------- launch ------------------------------------------------------
// NOTE launch order: up_gemm is the 6th launch so ncu (-s 5 -c 1) profiles it.
extern "C" void kernel_launch(void* const* d_in, const int* in_sizes, int n_in,
                              void* d_out, int out_size) {
    const float* x   = (const float*)d_in[0];
    const int*   idx = (const int*)d_in[1];
    const float* ew  = (const float*)d_in[2];
    const float* w1  = (const float*)d_in[3];
    const float* w2  = (const float*)d_in[4];
    const float* w3  = (const float*)d_in[5];
    float* out = (float*)d_out;

    cudaFuncSetAttribute(gemm_k<true>,  cudaFuncAttributeMaxDynamicSharedMemorySize, SMEMSZ);
    cudaFuncSetAttribute(gemm_k<false>, cudaFuncAttributeMaxDynamicSharedMemorySize, SMEMSZ);

    __half *xf, *w1f, *w2f, *w3f;
    cudaGetSymbolAddress((void**)&xf,  g_xf);
    cudaGetSymbolAddress((void**)&w1f, g_w1f);
    cudaGetSymbolAddress((void**)&w2f, g_w2f);
    cudaGetSymbolAddress((void**)&w3f, g_w3f);
    const int nw4 = NE * DM * DF / 4;
    const int nx4 = NT * DM / 4;
    const int CVTG = 2048;   // grid-stride: ~16 iters for weights

    reset_counts_k<<<1, 32>>>();                                        // 1
    route_k<<<NA / 256, 256>>>(idx);                                    // 2
    cvt_f16_k<<<(nx4 + 255) / 256, 256>>>((const float4*)x, (uint2*)xf, nx4);  // 3
    cvt_f16_k<<<CVTG, 256>>>((const float4*)w1, (uint2*)w1f, nw4);      // 4
    cvt_f16_k<<<CVTG, 256>>>((const float4*)w2, (uint2*)w2f, nw4);      // 5
    gemm_k<true><<<dim3(64, NA / BM, NE), 128, SMEMSZ>>>(ew);           // 6 <- ncu
    cvt_f16_k<<<CVTG, 256>>>((const float4*)w3, (uint2*)w3f, nw4);      // 7
    gemm_k<false><<<dim3(8, NA / BM, NE), 128, SMEMSZ>>>(ew);           // 8
    combine_k<<<(NT * (DM / 4) + 255) / 256, 256>>>(out);               // 9
}